// round 11
// baseline (speedup 1.0000x reference)
#include <cuda_runtime.h>
#include <cuda_bf16.h>

// Problem constants
#define Bc 2
#define Nc 96
#define NNc 9216            // Nc*Nc
#define Dc 64
#define Hc 4
#define DKc 16
#define ROWS_TOTAL 18432    // Bc*NNc

// Scratch (device globals; allocation-free per harness rules)
// g_proj layout: [proj(4)][b(2)][h(4)][i(9216)][d(16)]  (proj==1 slot unused)
__device__ float g_proj[4u * Bc * Hc * NNc * DKc];          // 18.9 MB
// rk transposed: [b][h][a(96)][d(16)][y(96)]
__device__ float g_rkT[(size_t)Bc * Hc * Nc * DKc * Nc];    // 4.7 MB
__device__ float g_attout[(size_t)ROWS_TOTAL * Dc];         // 4.7 MB

// ---------------------------------------------------------------------------
// Kernel A: projection.  32 rows x 64 cols per block, 128 threads, 4x4 tile.
// proj==1 blocks transpose their tile in smem (reusing w_s) and write g_rkT
// directly with coalesced 128B segments — no separate transpose kernel.
// ---------------------------------------------------------------------------
#define A_WS_STRIDE 68
#define T_STRIDE 36          // transpose buffer stride (float4-aligned)

__global__ void __launch_bounds__(128)
proj_kernel(const float* __restrict__ state,
            const float* __restrict__ w_lk, const float* __restrict__ b_lk,
            const float* __restrict__ w_rk, const float* __restrict__ b_rk,
            const float* __restrict__ w_lv, const float* __restrict__ b_lv,
            const float* __restrict__ w_rv, const float* __restrict__ b_rv)
{
    __shared__ __align__(16) float w_s[64 * A_WS_STRIDE];   // also transpose buf
    __shared__ __align__(16) float st_s[32 * 64];
    __shared__ float bias_s[64];

    const int tid = threadIdx.x;
    const int rowBase = blockIdx.x * 32;
    const int proj = blockIdx.y;

    const float* W = (proj == 0) ? w_lk : (proj == 1) ? w_rk
                    : (proj == 2) ? w_lv : w_rv;
    const float* Bv = (proj == 0) ? b_lk : (proj == 1) ? b_rk
                     : (proj == 2) ? b_lv : b_rv;

    // Weights transposed: w_s[k][p] = W[p][k]
    for (int idx = tid; idx < 4096; idx += 128) {
        int p = idx >> 6, k = idx & 63;
        w_s[k * A_WS_STRIDE + p] = W[idx];
    }
    if (tid < 64) bias_s[tid] = Bv[tid];
    {
        const float4* src = (const float4*)(state + (size_t)rowBase * 64);
        float4* dst = (float4*)st_s;
#pragma unroll
        for (int i = 0; i < 4; ++i) dst[tid + i * 128] = src[tid + i * 128];
    }
    __syncthreads();

    const int p0 = (tid & 15) * 4;   // 16 col groups
    const int r0 = (tid >> 4) * 4;   // 8 row groups

    float acc[4][4];
#pragma unroll
    for (int i = 0; i < 4; ++i)
#pragma unroll
        for (int j = 0; j < 4; ++j) acc[i][j] = 0.f;

#pragma unroll 8
    for (int k = 0; k < 64; ++k) {
        float4 wv = *(const float4*)&w_s[k * A_WS_STRIDE + p0];
#pragma unroll
        for (int i = 0; i < 4; ++i) {
            float s = st_s[(r0 + i) * 64 + k];
            acc[i][0] += s * wv.x;
            acc[i][1] += s * wv.y;
            acc[i][2] += s * wv.z;
            acc[i][3] += s * wv.w;
        }
    }

    const float4 bv = *(const float4*)&bias_s[p0];
    const int b   = rowBase / NNc;
    const int idx0 = rowBase - b * NNc;

    if (proj == 1) {
        // ---- transpose through smem, write g_rkT[b][h][a][d][y] coalesced
        __syncthreads();                 // everyone done reading w_s
        float* t = w_s;                  // 64 x T_STRIDE
#pragma unroll
        for (int i = 0; i < 4; ++i) {
            t[(p0 + 0) * T_STRIDE + r0 + i] = acc[i][0] + bv.x;
            t[(p0 + 1) * T_STRIDE + r0 + i] = acc[i][1] + bv.y;
            t[(p0 + 2) * T_STRIDE + r0 + i] = acc[i][2] + bv.z;
            t[(p0 + 3) * T_STRIDE + r0 + i] = acc[i][3] + bv.w;
        }
        __syncthreads();

        const int a  = idx0 / 96;
        const int y0 = idx0 - a * 96;    // 0, 32 or 64 (tile is within one a)
#pragma unroll
        for (int r = 0; r < 4; ++r) {
            int ii = tid + r * 128;      // 512 float4 total
            int p  = ii >> 3;            // 0..63  (h,d)
            int yq = ii & 7;             // 0..7
            float4 v = *(const float4*)&t[p * T_STRIDE + yq * 4];
            int h = p >> 4, d = p & 15;
            size_t off = ((((size_t)(b * Hc + h) * Nc + a) * DKc + d) * Nc)
                       + y0 + yq * 4;
            *(float4*)&g_rkT[off] = v;
        }
    } else {
        const int h  = p0 >> 4;
        const int d0 = p0 & 15;
#pragma unroll
        for (int i = 0; i < 4; ++i) {
            int idx = idx0 + r0 + i;
            float4 v;
            v.x = acc[i][0] + bv.x;
            v.y = acc[i][1] + bv.y;
            v.z = acc[i][2] + bv.z;
            v.w = acc[i][3] + bv.w;
            size_t off = ((size_t)((proj * Bc + b) * Hc + h) * NNc + idx) * DKc + d0;
            *(float4*)&g_proj[off] = v;
        }
    }
}

// ---------------------------------------------------------------------------
// Kernel B: streaming edge-attention, no-max softmax (R9/R10 proven).
// ---------------------------------------------------------------------------
#define TXB 6
#define YB  32
#define ACH 24
#define CF4 (TXB * ACH * DKc / 4)   // 576 float4 per lk/lv chunk

__global__ void __launch_bounds__(384, 3)
attn_kernel()
{
    __shared__ __align__(16) float lk_s[TXB * ACH * DKc];   // 2304
    __shared__ __align__(16) float lv_s[TXB * ACH * DKc];   // 2304
    __shared__ __align__(16) float sc_s[TXB * ACH * YB];    // 4608
    float* part = lk_s;
    float* pden = sc_s + 1024;

    const int tid = threadIdx.x;
    const int yt = blockIdx.x % 3;
    const int xt = (blockIdx.x / 3) & 15;
    const int bh = blockIdx.x / 48;
    const int h  = bh % Hc;
    const int b  = bh / Hc;
    const int x0 = xt * TXB;
    const int yb = yt * YB;

    const int slab = NNc * DKc;  // 147456
    const float* lkbase = g_proj + (size_t)((0 * Bc + b) * Hc + h) * slab;
    const float* lvbase = g_proj + (size_t)((2 * Bc + b) * Hc + h) * slab;
    const float* rvbase = g_proj + (size_t)((3 * Bc + b) * Hc + h) * slab;
    const float* rkT    = g_rkT + (size_t)(b * Hc + h) * Nc * DKc * Nc;

    const int wA = tid >> 5;          // 0..11
    const int lA = tid & 31;          // y-lane
    const int as = tid >> 7;          // 0..2
    const int rr = tid & 127;
    const int yl = rr >> 2;           // 0..31
    const int dq = rr & 3;            // 0..3
    const int y  = yb + yl;

    float4 num[TXB];
    float  den[TXB];
#pragma unroll
    for (int t = 0; t < TXB; ++t) { num[t] = make_float4(0,0,0,0); den[t] = 0.f; }

    for (int a0 = 0; a0 < 96; a0 += ACH) {
        __syncthreads();

        for (int i = tid; i < 2 * CF4; i += 384) {
            int arr = i >= CF4;
            int j   = arr ? i - CF4 : i;
            int tx  = j / (ACH * DKc / 4);
            int k   = j - tx * (ACH * DKc / 4);
            const float* src = (arr ? lvbase : lkbase)
                             + (size_t)((x0 + tx) * 96 + a0) * DKc;
            float* dst = (arr ? lv_s : lk_s) + tx * (ACH * DKc);
            ((float4*)dst)[k] = ((const float4*)src)[k];
        }
        __syncthreads();

#pragma unroll
        for (int rep = 0; rep < 2; ++rep) {
            const int al = wA + rep * 12;
            const int a  = a0 + al;
            const float* rkp = rkT + ((size_t)a * DKc) * Nc + yb + lA;
            float ps[TXB];
            {
                float r[8];
#pragma unroll
                for (int d = 0; d < 8; ++d) r[d] = rkp[(size_t)d * Nc];
#pragma unroll
                for (int tx = 0; tx < TXB; ++tx) {
                    const float4* lp = (const float4*)(lk_s + (tx * ACH + al) * DKc);
                    float4 l0 = lp[0], l1 = lp[1];
                    ps[tx] = l0.x * r[0] + l0.y * r[1] + l0.z * r[2] + l0.w * r[3]
                           + l1.x * r[4] + l1.y * r[5] + l1.z * r[6] + l1.w * r[7];
                }
            }
            {
                float r[8];
#pragma unroll
                for (int d = 0; d < 8; ++d) r[d] = rkp[(size_t)(8 + d) * Nc];
#pragma unroll
                for (int tx = 0; tx < TXB; ++tx) {
                    const float4* lp = (const float4*)(lk_s + (tx * ACH + al) * DKc + 8);
                    float4 l2 = lp[0], l3 = lp[1];
                    float s = ps[tx]
                            + l2.x * r[0] + l2.y * r[1] + l2.z * r[2] + l2.w * r[3]
                            + l3.x * r[4] + l3.y * r[5] + l3.z * r[6] + l3.w * r[7];
                    sc_s[(tx * ACH + al) * YB + lA] = __expf(s * 0.25f);
                }
            }
        }
        __syncthreads();

#pragma unroll
        for (int j = 0; j < 8; ++j) {
            const int al = as * 8 + j;
            const int a  = a0 + al;
            float4 rv = *(const float4*)(rvbase + ((size_t)(a * 96 + y)) * DKc + dq * 4);
#pragma unroll
            for (int tx = 0; tx < TXB; ++tx) {
                float e = sc_s[(tx * ACH + al) * YB + yl];
                float4 v = *(const float4*)(lv_s + (tx * ACH + al) * DKc + dq * 4);
                num[tx].x += e * (v.x * rv.x);
                num[tx].y += e * (v.y * rv.y);
                num[tx].z += e * (v.z * rv.z);
                num[tx].w += e * (v.w * rv.w);
                den[tx]   += e;
            }
        }
    }

    __syncthreads();
#pragma unroll
    for (int step = 0; step < 3; ++step) {
        if (as == step) {
            float4* p4 = (float4*)part;
            if (step == 0) {
#pragma unroll
                for (int tx = 0; tx < TXB; ++tx) {
                    p4[(tx * YB + yl) * 4 + dq] = num[tx];
                    if (dq == 0) pden[tx * YB + yl] = den[tx];
                }
            } else {
#pragma unroll
                for (int tx = 0; tx < TXB; ++tx) {
                    float4 c = p4[(tx * YB + yl) * 4 + dq];
                    c.x += num[tx].x; c.y += num[tx].y;
                    c.z += num[tx].z; c.w += num[tx].w;
                    p4[(tx * YB + yl) * 4 + dq] = c;
                    if (dq == 0) pden[tx * YB + yl] += den[tx];
                }
            }
        }
        __syncthreads();
    }

    {
        const float4* p4 = (const float4*)part;
#pragma unroll
        for (int r = 0; r < 2; ++r) {
            int idx = tid + r * 384;
            int dqo = idx & 3;
            int cyl = (idx >> 2) & 31;
            int tx  = idx >> 7;
            float inv = 1.f / pden[tx * YB + cyl];
            float4 o = p4[idx];
            o.x *= inv; o.y *= inv; o.z *= inv; o.w *= inv;
            size_t row = (size_t)b * NNc + (size_t)(x0 + tx) * 96 + (yb + cyl);
            *(float4*)&g_attout[row * 64 + h * 16 + dqo * 4] = o;
        }
    }
}

// ---------------------------------------------------------------------------
// Kernel C: output projection, p-split.  32 rows x 32 cols per block,
// 128 threads (2 rows x 4 cols per thread).  grid 1152 -> ~8 blocks/SM.
// ---------------------------------------------------------------------------
#define C_WS_STRIDE 36

__global__ void __launch_bounds__(128)
out_kernel(const float* __restrict__ w_out, const float* __restrict__ b_out,
           float* __restrict__ out)
{
    __shared__ __align__(16) float w_s[64 * C_WS_STRIDE];
    __shared__ __align__(16) float st_s[32 * 64];
    __shared__ float bias_s[32];

    const int tid = threadIdx.x;
    const int rowBase = (blockIdx.x >> 1) * 32;
    const int pBase   = (blockIdx.x & 1) * 32;

    // Weights transposed: w_s[k][pl] = w_out[pBase+pl][k]   (32 cols)
    for (int idx = tid; idx < 2048; idx += 128) {
        int pl = idx >> 6, k = idx & 63;
        w_s[k * C_WS_STRIDE + pl] = w_out[(pBase + pl) * 64 + k];
    }
    if (tid < 32) bias_s[tid] = b_out[pBase + tid];
    {
        const float4* src = (const float4*)(g_attout + (size_t)rowBase * 64);
        float4* dst = (float4*)st_s;
#pragma unroll
        for (int i = 0; i < 4; ++i) dst[tid + i * 128] = src[tid + i * 128];
    }
    __syncthreads();

    const int p0 = (tid & 7) * 4;    // 8 col groups (local)
    const int r0 = (tid >> 3) * 2;   // 16 row groups, 2 rows each

    float acc[2][4];
#pragma unroll
    for (int i = 0; i < 2; ++i)
#pragma unroll
        for (int j = 0; j < 4; ++j) acc[i][j] = 0.f;

#pragma unroll 8
    for (int k = 0; k < 64; ++k) {
        float4 wv = *(const float4*)&w_s[k * C_WS_STRIDE + p0];
        float s0 = st_s[(r0 + 0) * 64 + k];
        float s1 = st_s[(r0 + 1) * 64 + k];
        acc[0][0] += s0 * wv.x; acc[0][1] += s0 * wv.y;
        acc[0][2] += s0 * wv.z; acc[0][3] += s0 * wv.w;
        acc[1][0] += s1 * wv.x; acc[1][1] += s1 * wv.y;
        acc[1][2] += s1 * wv.z; acc[1][3] += s1 * wv.w;
    }

    const float4 bv = *(const float4*)&bias_s[p0];
#pragma unroll
    for (int i = 0; i < 2; ++i) {
        int row = rowBase + r0 + i;
        float4 v;
        v.x = acc[i][0] + bv.x;
        v.y = acc[i][1] + bv.y;
        v.z = acc[i][2] + bv.z;
        v.w = acc[i][3] + bv.w;
        *(float4*)&out[(size_t)row * 64 + pBase + p0] = v;
    }
}

// ---------------------------------------------------------------------------
extern "C" void kernel_launch(void* const* d_in, const int* in_sizes, int n_in,
                              void* d_out, int out_size)
{
    const float* state = (const float*)d_in[0];
    const float* w_lk = (const float*)d_in[1];
    const float* b_lk = (const float*)d_in[2];
    const float* w_rk = (const float*)d_in[3];
    const float* b_rk = (const float*)d_in[4];
    const float* w_lv = (const float*)d_in[5];
    const float* b_lv = (const float*)d_in[6];
    const float* w_rv = (const float*)d_in[7];
    const float* b_rv = (const float*)d_in[8];
    const float* w_out = (const float*)d_in[9];
    const float* b_out = (const float*)d_in[10];
    float* out = (float*)d_out;

    dim3 gridA(ROWS_TOTAL / 32, 4);
    proj_kernel<<<gridA, 128>>>(
        state, w_lk, b_lk, w_rk, b_rk, w_lv, b_lv, w_rv, b_rv);

    attn_kernel<<<Bc * Hc * (Nc / TXB) * (Nc / YB), 384>>>();

    out_kernel<<<(ROWS_TOTAL / 32) * 2, 128>>>(w_out, b_out, out);
}

// round 12
// speedup vs baseline: 1.0586x; 1.0586x over previous
#include <cuda_runtime.h>
#include <cuda_bf16.h>

// Problem constants
#define Bc 2
#define Nc 96
#define NNc 9216            // Nc*Nc
#define Dc 64
#define Hc 4
#define DKc 16
#define ROWS_TOTAL 18432    // Bc*NNc

// Scratch (device globals; allocation-free per harness rules)
// g_proj layout: [proj(4)][b(2)][h(4)][i(9216)][d(16)]  (proj==1 slot unused)
__device__ float g_proj[4u * Bc * Hc * NNc * DKc];          // 18.9 MB
// rk transposed: [b][h][a(96)][d(16)][y(96)]
__device__ float g_rkT[(size_t)Bc * Hc * Nc * DKc * Nc];    // 4.7 MB
__device__ float g_attout[(size_t)ROWS_TOTAL * Dc];         // 4.7 MB

// ---------------------------------------------------------------------------
// Kernel A: projection.  32 rows x 64 cols per block, 128 threads, 4x4 tile.
// proj==1 blocks transpose their tile in smem (reusing w_s) and write g_rkT
// directly with coalesced 128B segments — no separate transpose kernel.
// (R11 proven: 27.1us, issue 50%)
// ---------------------------------------------------------------------------
#define A_WS_STRIDE 68
#define T_STRIDE 36          // transpose buffer stride (float4-aligned)

__global__ void __launch_bounds__(128)
proj_kernel(const float* __restrict__ state,
            const float* __restrict__ w_lk, const float* __restrict__ b_lk,
            const float* __restrict__ w_rk, const float* __restrict__ b_rk,
            const float* __restrict__ w_lv, const float* __restrict__ b_lv,
            const float* __restrict__ w_rv, const float* __restrict__ b_rv)
{
    __shared__ __align__(16) float w_s[64 * A_WS_STRIDE];   // also transpose buf
    __shared__ __align__(16) float st_s[32 * 64];
    __shared__ float bias_s[64];

    const int tid = threadIdx.x;
    const int rowBase = blockIdx.x * 32;
    const int proj = blockIdx.y;

    const float* W = (proj == 0) ? w_lk : (proj == 1) ? w_rk
                    : (proj == 2) ? w_lv : w_rv;
    const float* Bv = (proj == 0) ? b_lk : (proj == 1) ? b_rk
                     : (proj == 2) ? b_lv : b_rv;

    // Weights transposed: w_s[k][p] = W[p][k]
    for (int idx = tid; idx < 4096; idx += 128) {
        int p = idx >> 6, k = idx & 63;
        w_s[k * A_WS_STRIDE + p] = W[idx];
    }
    if (tid < 64) bias_s[tid] = Bv[tid];
    {
        const float4* src = (const float4*)(state + (size_t)rowBase * 64);
        float4* dst = (float4*)st_s;
#pragma unroll
        for (int i = 0; i < 4; ++i) dst[tid + i * 128] = src[tid + i * 128];
    }
    __syncthreads();

    const int p0 = (tid & 15) * 4;   // 16 col groups
    const int r0 = (tid >> 4) * 4;   // 8 row groups

    float acc[4][4];
#pragma unroll
    for (int i = 0; i < 4; ++i)
#pragma unroll
        for (int j = 0; j < 4; ++j) acc[i][j] = 0.f;

#pragma unroll 8
    for (int k = 0; k < 64; ++k) {
        float4 wv = *(const float4*)&w_s[k * A_WS_STRIDE + p0];
#pragma unroll
        for (int i = 0; i < 4; ++i) {
            float s = st_s[(r0 + i) * 64 + k];
            acc[i][0] += s * wv.x;
            acc[i][1] += s * wv.y;
            acc[i][2] += s * wv.z;
            acc[i][3] += s * wv.w;
        }
    }

    const float4 bv = *(const float4*)&bias_s[p0];
    const int b   = rowBase / NNc;
    const int idx0 = rowBase - b * NNc;

    if (proj == 1) {
        // ---- transpose through smem, write g_rkT[b][h][a][d][y] coalesced
        __syncthreads();                 // everyone done reading w_s
        float* t = w_s;                  // 64 x T_STRIDE
#pragma unroll
        for (int i = 0; i < 4; ++i) {
            t[(p0 + 0) * T_STRIDE + r0 + i] = acc[i][0] + bv.x;
            t[(p0 + 1) * T_STRIDE + r0 + i] = acc[i][1] + bv.y;
            t[(p0 + 2) * T_STRIDE + r0 + i] = acc[i][2] + bv.z;
            t[(p0 + 3) * T_STRIDE + r0 + i] = acc[i][3] + bv.w;
        }
        __syncthreads();

        const int a  = idx0 / 96;
        const int y0 = idx0 - a * 96;    // 0, 32 or 64 (tile is within one a)
#pragma unroll
        for (int r = 0; r < 4; ++r) {
            int ii = tid + r * 128;      // 512 float4 total
            int p  = ii >> 3;            // 0..63  (h,d)
            int yq = ii & 7;             // 0..7
            float4 v = *(const float4*)&t[p * T_STRIDE + yq * 4];
            int h = p >> 4, d = p & 15;
            size_t off = ((((size_t)(b * Hc + h) * Nc + a) * DKc + d) * Nc)
                       + y0 + yq * 4;
            *(float4*)&g_rkT[off] = v;
        }
    } else {
        const int h  = p0 >> 4;
        const int d0 = p0 & 15;
#pragma unroll
        for (int i = 0; i < 4; ++i) {
            int idx = idx0 + r0 + i;
            float4 v;
            v.x = acc[i][0] + bv.x;
            v.y = acc[i][1] + bv.y;
            v.z = acc[i][2] + bv.z;
            v.w = acc[i][3] + bv.w;
            size_t off = ((size_t)((proj * Bc + b) * Hc + h) * NNc + idx) * DKc + d0;
            *(float4*)&g_proj[off] = v;
        }
    }
}

// ---------------------------------------------------------------------------
// Kernel B: streaming edge-attention, no-max softmax (R9/R10 proven).
// ---------------------------------------------------------------------------
#define TXB 6
#define YB  32
#define ACH 24
#define CF4 (TXB * ACH * DKc / 4)   // 576 float4 per lk/lv chunk

__global__ void __launch_bounds__(384, 3)
attn_kernel()
{
    __shared__ __align__(16) float lk_s[TXB * ACH * DKc];   // 2304
    __shared__ __align__(16) float lv_s[TXB * ACH * DKc];   // 2304
    __shared__ __align__(16) float sc_s[TXB * ACH * YB];    // 4608
    float* part = lk_s;
    float* pden = sc_s + 1024;

    const int tid = threadIdx.x;
    const int yt = blockIdx.x % 3;
    const int xt = (blockIdx.x / 3) & 15;
    const int bh = blockIdx.x / 48;
    const int h  = bh % Hc;
    const int b  = bh / Hc;
    const int x0 = xt * TXB;
    const int yb = yt * YB;

    const int slab = NNc * DKc;  // 147456
    const float* lkbase = g_proj + (size_t)((0 * Bc + b) * Hc + h) * slab;
    const float* lvbase = g_proj + (size_t)((2 * Bc + b) * Hc + h) * slab;
    const float* rvbase = g_proj + (size_t)((3 * Bc + b) * Hc + h) * slab;
    const float* rkT    = g_rkT + (size_t)(b * Hc + h) * Nc * DKc * Nc;

    const int wA = tid >> 5;          // 0..11
    const int lA = tid & 31;          // y-lane
    const int as = tid >> 7;          // 0..2
    const int rr = tid & 127;
    const int yl = rr >> 2;           // 0..31
    const int dq = rr & 3;            // 0..3
    const int y  = yb + yl;

    float4 num[TXB];
    float  den[TXB];
#pragma unroll
    for (int t = 0; t < TXB; ++t) { num[t] = make_float4(0,0,0,0); den[t] = 0.f; }

    for (int a0 = 0; a0 < 96; a0 += ACH) {
        __syncthreads();

        for (int i = tid; i < 2 * CF4; i += 384) {
            int arr = i >= CF4;
            int j   = arr ? i - CF4 : i;
            int tx  = j / (ACH * DKc / 4);
            int k   = j - tx * (ACH * DKc / 4);
            const float* src = (arr ? lvbase : lkbase)
                             + (size_t)((x0 + tx) * 96 + a0) * DKc;
            float* dst = (arr ? lv_s : lk_s) + tx * (ACH * DKc);
            ((float4*)dst)[k] = ((const float4*)src)[k];
        }
        __syncthreads();

#pragma unroll
        for (int rep = 0; rep < 2; ++rep) {
            const int al = wA + rep * 12;
            const int a  = a0 + al;
            const float* rkp = rkT + ((size_t)a * DKc) * Nc + yb + lA;
            float ps[TXB];
            {
                float r[8];
#pragma unroll
                for (int d = 0; d < 8; ++d) r[d] = rkp[(size_t)d * Nc];
#pragma unroll
                for (int tx = 0; tx < TXB; ++tx) {
                    const float4* lp = (const float4*)(lk_s + (tx * ACH + al) * DKc);
                    float4 l0 = lp[0], l1 = lp[1];
                    ps[tx] = l0.x * r[0] + l0.y * r[1] + l0.z * r[2] + l0.w * r[3]
                           + l1.x * r[4] + l1.y * r[5] + l1.z * r[6] + l1.w * r[7];
                }
            }
            {
                float r[8];
#pragma unroll
                for (int d = 0; d < 8; ++d) r[d] = rkp[(size_t)(8 + d) * Nc];
#pragma unroll
                for (int tx = 0; tx < TXB; ++tx) {
                    const float4* lp = (const float4*)(lk_s + (tx * ACH + al) * DKc + 8);
                    float4 l2 = lp[0], l3 = lp[1];
                    float s = ps[tx]
                            + l2.x * r[0] + l2.y * r[1] + l2.z * r[2] + l2.w * r[3]
                            + l3.x * r[4] + l3.y * r[5] + l3.z * r[6] + l3.w * r[7];
                    sc_s[(tx * ACH + al) * YB + lA] = __expf(s * 0.25f);
                }
            }
        }
        __syncthreads();

#pragma unroll
        for (int j = 0; j < 8; ++j) {
            const int al = as * 8 + j;
            const int a  = a0 + al;
            float4 rv = *(const float4*)(rvbase + ((size_t)(a * 96 + y)) * DKc + dq * 4);
#pragma unroll
            for (int tx = 0; tx < TXB; ++tx) {
                float e = sc_s[(tx * ACH + al) * YB + yl];
                float4 v = *(const float4*)(lv_s + (tx * ACH + al) * DKc + dq * 4);
                num[tx].x += e * (v.x * rv.x);
                num[tx].y += e * (v.y * rv.y);
                num[tx].z += e * (v.z * rv.z);
                num[tx].w += e * (v.w * rv.w);
                den[tx]   += e;
            }
        }
    }

    __syncthreads();
#pragma unroll
    for (int step = 0; step < 3; ++step) {
        if (as == step) {
            float4* p4 = (float4*)part;
            if (step == 0) {
#pragma unroll
                for (int tx = 0; tx < TXB; ++tx) {
                    p4[(tx * YB + yl) * 4 + dq] = num[tx];
                    if (dq == 0) pden[tx * YB + yl] = den[tx];
                }
            } else {
#pragma unroll
                for (int tx = 0; tx < TXB; ++tx) {
                    float4 c = p4[(tx * YB + yl) * 4 + dq];
                    c.x += num[tx].x; c.y += num[tx].y;
                    c.z += num[tx].z; c.w += num[tx].w;
                    p4[(tx * YB + yl) * 4 + dq] = c;
                    if (dq == 0) pden[tx * YB + yl] += den[tx];
                }
            }
        }
        __syncthreads();
    }

    {
        const float4* p4 = (const float4*)part;
#pragma unroll
        for (int r = 0; r < 2; ++r) {
            int idx = tid + r * 384;
            int dqo = idx & 3;
            int cyl = (idx >> 2) & 31;
            int tx  = idx >> 7;
            float inv = 1.f / pden[tx * YB + cyl];
            float4 o = p4[idx];
            o.x *= inv; o.y *= inv; o.z *= inv; o.w *= inv;
            size_t row = (size_t)b * NNc + (size_t)(x0 + tx) * 96 + (yb + cyl);
            *(float4*)&g_attout[row * 64 + h * 16 + dqo * 4] = o;
        }
    }
}

// ---------------------------------------------------------------------------
// Kernel C: output projection.  32 rows x 64 cols per block, 128 threads,
// 4x4 tile (R10 proven: 12.3us).
// ---------------------------------------------------------------------------
__global__ void __launch_bounds__(128)
out_kernel(const float* __restrict__ w_out, const float* __restrict__ b_out,
           float* __restrict__ out)
{
    __shared__ __align__(16) float w_s[64 * A_WS_STRIDE];
    __shared__ __align__(16) float st_s[32 * 64];
    __shared__ float bias_s[64];

    const int tid = threadIdx.x;
    const int rowBase = blockIdx.x * 32;

    for (int idx = tid; idx < 4096; idx += 128) {
        int p = idx >> 6, k = idx & 63;
        w_s[k * A_WS_STRIDE + p] = w_out[idx];
    }
    if (tid < 64) bias_s[tid] = b_out[tid];
    {
        const float4* src = (const float4*)(g_attout + (size_t)rowBase * 64);
        float4* dst = (float4*)st_s;
#pragma unroll
        for (int i = 0; i < 4; ++i) dst[tid + i * 128] = src[tid + i * 128];
    }
    __syncthreads();

    const int p0 = (tid & 15) * 4;
    const int r0 = (tid >> 4) * 4;

    float acc[4][4];
#pragma unroll
    for (int i = 0; i < 4; ++i)
#pragma unroll
        for (int j = 0; j < 4; ++j) acc[i][j] = 0.f;

#pragma unroll 8
    for (int k = 0; k < 64; ++k) {
        float4 wv = *(const float4*)&w_s[k * A_WS_STRIDE + p0];
#pragma unroll
        for (int i = 0; i < 4; ++i) {
            float s = st_s[(r0 + i) * 64 + k];
            acc[i][0] += s * wv.x;
            acc[i][1] += s * wv.y;
            acc[i][2] += s * wv.z;
            acc[i][3] += s * wv.w;
        }
    }

    const float4 bv = *(const float4*)&bias_s[p0];
#pragma unroll
    for (int i = 0; i < 4; ++i) {
        int row = rowBase + r0 + i;
        float4 v;
        v.x = acc[i][0] + bv.x;
        v.y = acc[i][1] + bv.y;
        v.z = acc[i][2] + bv.z;
        v.w = acc[i][3] + bv.w;
        *(float4*)&out[(size_t)row * 64 + p0] = v;
    }
}

// ---------------------------------------------------------------------------
extern "C" void kernel_launch(void* const* d_in, const int* in_sizes, int n_in,
                              void* d_out, int out_size)
{
    const float* state = (const float*)d_in[0];
    const float* w_lk = (const float*)d_in[1];
    const float* b_lk = (const float*)d_in[2];
    const float* w_rk = (const float*)d_in[3];
    const float* b_rk = (const float*)d_in[4];
    const float* w_lv = (const float*)d_in[5];
    const float* b_lv = (const float*)d_in[6];
    const float* w_rv = (const float*)d_in[7];
    const float* b_rv = (const float*)d_in[8];
    const float* w_out = (const float*)d_in[9];
    const float* b_out = (const float*)d_in[10];
    float* out = (float*)d_out;

    dim3 gridA(ROWS_TOTAL / 32, 4);
    proj_kernel<<<gridA, 128>>>(
        state, w_lk, b_lk, w_rk, b_rk, w_lv, b_lv, w_rv, b_rv);

    attn_kernel<<<Bc * Hc * (Nc / TXB) * (Nc / YB), 384>>>();

    out_kernel<<<ROWS_TOTAL / 32, 128>>>(w_out, b_out, out);
}